// round 15
// baseline (speedup 1.0000x reference)
#include <cuda_runtime.h>
#include <cuda_fp16.h>
#include <cstdint>

#define NTHR 256

// ---- shared memory byte offsets ----
#define BB_HI 0                 // W2 [j][k] fp16 (both GEMMs), 32KB
#define H1_OF (32*1024)         // H1 tile [s][j] fp16, 128 rows, 32KB
#define G2_OF (64*1024)         // G2 tile [s][k] fp16, 128 rows, 32KB
#define OW1   (96*1024)         // 4*128 floats
#define OB1   (OW1 + 2048)
#define OB2   (OB1 + 512)
#define OW3   (OB2 + 512)
#define OTRIG (OW3 + 512)       // 128 * 8 floats = 4KB
#define OPF   (OTRIG + 128*8*4) // 4 * 128 * 4 floats = 8KB
#define SMEM_TOTAL (OPF + 4*128*4*4)

__device__ __forceinline__ uint32_t smem_u32(const void* p) {
    uint32_t a;
    asm("{ .reg .u64 t; cvta.to.shared.u64 t, %1; cvt.u32.u64 %0, t; }"
        : "=r"(a) : "l"(p));
    return a;
}
__device__ __forceinline__ float ftanh(float x) {
    float y;
    asm("tanh.approx.f32 %0, %1;" : "=f"(y) : "f"(x));
    return y;
}
// group-scoped barrier: 128 threads, barrier id 1+mg (per-CTA resource)
__device__ __forceinline__ void gbar(int mg) {
    asm volatile("bar.sync %0, 128;" :: "r"(1 + mg) : "memory");
}
// swizzled byte offset of 16B chunk (row r, chunk) in a [rows]x128 fp16 tile
__device__ __forceinline__ uint32_t swz(int r, int chunk) {
    return (uint32_t)((r << 8) + (((chunk ^ (r & 7)) & 15) << 4));
}
__device__ __forceinline__ uint32_t helem(int r, int c) {
    return swz(r, c >> 3) + ((c & 7) << 1);
}
__device__ __forceinline__ uint32_t packh2(float x0, float x1) {
    const __half2 h = __floats2half2_rn(x0, x1);
    return *(const uint32_t*)&h;
}
__device__ __forceinline__ void ldsm4(uint32_t& r0, uint32_t& r1,
                                      uint32_t& r2, uint32_t& r3, uint32_t a) {
    asm volatile("ldmatrix.sync.aligned.m8n8.x4.shared.b16 {%0,%1,%2,%3}, [%4];"
                 : "=r"(r0), "=r"(r1), "=r"(r2), "=r"(r3) : "r"(a));
}
__device__ __forceinline__ void ldsm4t(uint32_t& r0, uint32_t& r1,
                                       uint32_t& r2, uint32_t& r3, uint32_t a) {
    asm volatile("ldmatrix.sync.aligned.m8n8.x4.trans.shared.b16 {%0,%1,%2,%3}, [%4];"
                 : "=r"(r0), "=r"(r1), "=r"(r2), "=r"(r3) : "r"(a));
}
__device__ __forceinline__ void stsm4(uint32_t a, uint32_t r0, uint32_t r1,
                                      uint32_t r2, uint32_t r3) {
    asm volatile("stmatrix.sync.aligned.m8n8.x4.shared.b16 [%0], {%1,%2,%3,%4};"
                 :: "r"(a), "r"(r0), "r"(r1), "r"(r2), "r"(r3) : "memory");
}
__device__ __forceinline__ void mma16816(float d[4],
                                         uint32_t a0, uint32_t a1,
                                         uint32_t a2, uint32_t a3,
                                         uint32_t b0, uint32_t b1) {
    asm volatile(
        "mma.sync.aligned.m16n8k16.row.col.f32.f16.f16.f32 "
        "{%0,%1,%2,%3}, {%4,%5,%6,%7}, {%8,%9}, {%0,%1,%2,%3};"
        : "+f"(d[0]), "+f"(d[1]), "+f"(d[2]), "+f"(d[3])
        : "r"(a0), "r"(a1), "r"(a2), "r"(a3), "r"(b0), "r"(b1));
}

// D(64x128) rows [mbase,mbase+64) = A-rows @ op(B); plain fp16.
// Warp computes m64 x n32 (mt=4). TRANSB: B memory [kdim][n]; else [n][kdim].
template <bool TRANSB>
__device__ __forceinline__ void gemm_tile(uint32_t sb, uint32_t Aoff, uint32_t Bo,
                                          int mbase, int nbase, int lane,
                                          float acc[4][4][4]) {
    #pragma unroll
    for (int mt = 0; mt < 4; mt++)
        #pragma unroll
        for (int nt = 0; nt < 4; nt++)
            #pragma unroll
            for (int e = 0; e < 4; e++) acc[mt][nt][e] = 0.0f;

    #pragma unroll
    for (int k = 0; k < 8; k++) {
        const int cb = k * 2;
        uint32_t bH[4][2];
        #pragma unroll
        for (int p = 0; p < 2; p++) {
            const int ntl   = 2 * p + ((lane >> 4) & 1);
            const int khalf = (lane >> 3) & 1;
            if (TRANSB) {
                const int r = k * 16 + khalf * 8 + (lane & 7);
                const uint32_t off = swz(r, (nbase + ntl * 8) >> 3);
                ldsm4t(bH[2*p][0], bH[2*p][1], bH[2*p+1][0], bH[2*p+1][1],
                       sb + Bo + off);
            } else {
                const int r = nbase + ntl * 8 + (lane & 7);
                const uint32_t off = swz(r, cb + khalf);
                ldsm4(bH[2*p][0], bH[2*p][1], bH[2*p+1][0], bH[2*p+1][1],
                      sb + Bo + off);
            }
        }
        #pragma unroll
        for (int mt = 0; mt < 4; mt++) {
            uint32_t aH[4];
            const int r = mbase + mt * 16 + (lane & 15);
            const uint32_t off = swz(r, cb + (lane >> 4));
            ldsm4(aH[0], aH[1], aH[2], aH[3], sb + Aoff + off);
            #pragma unroll
            for (int nt = 0; nt < 4; nt++)
                mma16816(acc[mt][nt], aH[0], aH[1], aH[2], aH[3],
                         bH[nt][0], bH[nt][1]);
        }
    }
}

__global__ void __launch_bounds__(NTHR, 2)
lnn_kernel(const float* __restrict__ X,
           const float* __restrict__ W1, const float* __restrict__ b1,
           const float* __restrict__ W2, const float* __restrict__ b2,
           const float* __restrict__ W3,
           float* __restrict__ out, int B)
{
    extern __shared__ char smem[];
    const uint32_t sb = smem_u32(smem);
    const int tid  = threadIdx.x;
    const int wid  = tid >> 5;
    const int lane = tid & 31;

    // ---- stage W2 fp16 (single [j][k] layout) ----
    for (int idx = tid; idx < 128 * 128; idx += NTHR) {
        const int j = idx >> 7, k = idx & 127;
        const __half h = __float2half_rn(W2[idx]);
        *(uint16_t*)(smem + BB_HI + helem(j, k)) = __half_as_ushort(h);
    }
    {
        float* w1s = (float*)(smem + OW1);
        for (int i = tid; i < 512; i += NTHR) w1s[i] = W1[i];
        float* d1 = (float*)(smem + OB1);
        float* d2 = (float*)(smem + OB2);
        float* d3 = (float*)(smem + OW3);
        for (int i = tid; i < 128; i += NTHR) {
            d1[i] = b1[i]; d2[i] = b2[i]; d3[i] = W3[i];
        }
    }
    __syncthreads();   // only full-CTA sync; after this the two groups run free

    const float* w1p = (const float*)(smem + OW1);
    const float* b1p = (const float*)(smem + OB1);
    const float* b2p = (const float*)(smem + OB2);
    const float* w3p = (const float*)(smem + OW3);
    float* trig = (float*)(smem + OTRIG);
    float* pfb  = (float*)(smem + OPF);

    const int mg = wid >> 2, ng = wid & 3;     // group (pipeline) / n-column
    const int mbase = mg * 64, nbase = ng * 32;
    const int gt = tid & 127;                  // index within group

    // hoisted per-lane constants for epilogues
    float b2v[8], w3v[8], w1a[8][4];
    #pragma unroll
    for (int nt = 0; nt < 4; nt++) {
        const int c = nbase + nt * 8 + 2 * (lane & 3);
        #pragma unroll
        for (int e = 0; e < 2; e++) {
            const int j = c + e;
            b2v[nt * 2 + e] = b2p[j];
            w3v[nt * 2 + e] = w3p[j];
            w1a[nt * 2 + e][0] = w1p[j];
            w1a[nt * 2 + e][1] = w1p[128 + j];
            w1a[nt * 2 + e][2] = w1p[256 + j];
            w1a[nt * 2 + e][3] = w1p[384 + j];
        }
    }

    const int nTiles = (B + 127) >> 7;         // 128-sample tiles
    for (int t = blockIdx.x; t < nTiles; t += gridDim.x) {
        // ---- 1. trig + layer 1 (group rows only; 2 threads per row) ----
        {
            const int s = mbase + (gt >> 1);   // own-group sample row
            const int q = gt & 1;              // j-half (chunks q*8..q*8+7)
            const int g = (t << 7) + s;
            if (g < B) {
                const float4 x = reinterpret_cast<const float4*>(X)[g];
                float s1, c1, s2, c2;
                __sincosf(x.x, &s1, &c1);
                __sincosf(x.y, &s2, &c2);
                if (q == 0) {
                    float* tr = trig + s * 8;
                    tr[0] = s1; tr[1] = c1; tr[2] = s2; tr[3] = c2;
                    tr[4] = x.z; tr[5] = x.w;
                }
                #pragma unroll
                for (int qq = 0; qq < 8; qq++) {
                    const int cc = q * 8 + qq;
                    uint32_t hw[4];
                    #pragma unroll
                    for (int p = 0; p < 4; p++) {
                        const int j = cc * 8 + p * 2;
                        float z0 = b1p[j], z1 = b1p[j + 1];
                        z0 = fmaf(s1, w1p[j], z0);       z1 = fmaf(s1, w1p[j + 1], z1);
                        z0 = fmaf(c1, w1p[128 + j], z0); z1 = fmaf(c1, w1p[129 + j], z1);
                        z0 = fmaf(s2, w1p[256 + j], z0); z1 = fmaf(s2, w1p[257 + j], z1);
                        z0 = fmaf(c2, w1p[384 + j], z0); z1 = fmaf(c2, w1p[385 + j], z1);
                        hw[p] = packh2(ftanh(z0), ftanh(z1));
                    }
                    const uint32_t off = swz(s, cc);
                    *(uint4*)(smem + H1_OF + off) =
                        make_uint4(hw[0], hw[1], hw[2], hw[3]);
                }
            }
        }
        gbar(mg);

        // ---- 2. GEMM1: Z2 = H1 @ W2 (own rows; B via trans ldmatrix) ----
        float acc[4][4][4];
        gemm_tile<true>(sb, H1_OF, BB_HI, mbase, nbase, lane, acc);

        // ---- 3. epilogue 1: G2 = W3*(1-tanh(Z2+b2)^2) -> G2 (stmatrix) ----
        #pragma unroll
        for (int mt = 0; mt < 4; mt++)
            #pragma unroll
            for (int hf = 0; hf < 2; hf++) {
                uint32_t rr[4];
                #pragma unroll
                for (int nt = 0; nt < 4; nt++) {
                    const float z0 = acc[mt][nt][hf * 2]     + b2v[nt * 2];
                    const float z1 = acc[mt][nt][hf * 2 + 1] + b2v[nt * 2 + 1];
                    const float t0 = ftanh(z0), t1 = ftanh(z1);
                    const float g0 = w3v[nt * 2]     * (1.0f - t0 * t0);
                    const float g1 = w3v[nt * 2 + 1] * (1.0f - t1 * t1);
                    rr[nt] = packh2(g0, g1);
                }
                const int row = mbase + mt * 16 + hf * 8 + (lane & 7);
                const uint32_t addr =
                    sb + G2_OF + swz(row, (nbase >> 3) + (lane >> 3));
                stsm4(addr, rr[0], rr[1], rr[2], rr[3]);
            }
        gbar(mg);

        // ---- 4. GEMM2: G1pre = G2 @ W2^T (own rows; B non-trans) ----
        gemm_tile<false>(sb, G2_OF, BB_HI, mbase, nbase, lane, acc);

        // ---- 5. epilogue 2: h1 fragments via ldmatrix; pf_i = sum W1*g1 ----
        #pragma unroll
        for (int mt = 0; mt < 4; mt++)
            #pragma unroll
            for (int hf = 0; hf < 2; hf++) {
                const int lrow = mbase + mt * 16 + hf * 8 + (lane & 7);
                uint32_t hfrag[4];
                ldsm4(hfrag[0], hfrag[1], hfrag[2], hfrag[3],
                      sb + H1_OF + swz(lrow, (nbase >> 3) + (lane >> 3)));
                float pf0 = 0.f, pf1 = 0.f, pf2 = 0.f, pf3 = 0.f;
                #pragma unroll
                for (int nt = 0; nt < 4; nt++) {
                    const float2 fh = __half22float2(*(const __half2*)&hfrag[nt]);
                    const float hv[2] = {fh.x, fh.y};
                    #pragma unroll
                    for (int e = 0; e < 2; e++) {
                        const float pre = acc[mt][nt][hf * 2 + e];
                        const float h = hv[e];
                        const float g1 = (1.0f - h * h) * pre;
                        const float* wa = w1a[nt * 2 + e];
                        pf0 = fmaf(wa[0], g1, pf0); pf1 = fmaf(wa[1], g1, pf1);
                        pf2 = fmaf(wa[2], g1, pf2); pf3 = fmaf(wa[3], g1, pf3);
                    }
                }
                pf0 += __shfl_xor_sync(0xffffffffu, pf0, 1);
                pf1 += __shfl_xor_sync(0xffffffffu, pf1, 1);
                pf2 += __shfl_xor_sync(0xffffffffu, pf2, 1);
                pf3 += __shfl_xor_sync(0xffffffffu, pf3, 1);
                pf0 += __shfl_xor_sync(0xffffffffu, pf0, 2);
                pf1 += __shfl_xor_sync(0xffffffffu, pf1, 2);
                pf2 += __shfl_xor_sync(0xffffffffu, pf2, 2);
                pf3 += __shfl_xor_sync(0xffffffffu, pf3, 2);
                const int row = mbase + mt * 16 + (lane >> 2) + hf * 8;
                if ((lane & 3) == 0)
                    *(float4*)(pfb + (ng * 128 + row) * 4) =
                        make_float4(pf0, pf1, pf2, pf3);
            }
        gbar(mg);

        // ---- 6. combine partials + analytic closure + 2x2 solve ----
        if (gt < 64) {
            const int row  = mbase + gt;       // own-group sample row
            const int gidx = (t << 7) + row;
            if (gidx < B) {
                float p0 = 0.f, p1 = 0.f, p2 = 0.f, p3 = 0.f;
                #pragma unroll
                for (int q = 0; q < 4; q++) {
                    const float4 v = *(const float4*)(pfb + (q * 128 + row) * 4);
                    p0 += v.x; p1 += v.y; p2 += v.z; p3 += v.w;
                }
                const float* tr = trig + row * 8;
                const float s1 = tr[0], c1 = tr[1], s2 = tr[2], c2 = tr[3];
                const float w1v = tr[4], w2v = tr[5];
                const float sd = s1 * c2 - c1 * s2;
                const float cd = c1 * c2 + s1 * s2;
                const float dV1 = p0 * c1 - p1 * s1;
                const float dV2 = p2 * c2 - p3 * s2;
                const float dw = w2v - w1v;
                const float rhs1 = -w1v * w2v * sd - dV1 - w2v * sd * dw;
                const float rhs2 =  w1v * w2v * sd - dV2 - w1v * sd * dw;
                const float det = 2.0f - cd * cd;
                const float inv = __fdividef(1.0f, det);
                const float q1 = (rhs1 - cd * rhs2) * inv;
                const float q2 = (2.0f * rhs2 - cd * rhs1) * inv;
                reinterpret_cast<float4*>(out)[gidx] = make_float4(w1v, w2v, q1, q2);
            }
        }
        gbar(mg);   // protect trig/pfb/H1 (own rows) before next tile
    }
}

extern "C" void kernel_launch(void* const* d_in, const int* in_sizes, int n_in,
                              void* d_out, int out_size)
{
    const float* X  = (const float*)d_in[0];
    const float* W1 = (const float*)d_in[1];
    const float* b1 = (const float*)d_in[2];
    const float* W2 = (const float*)d_in[3];
    const float* b2 = (const float*)d_in[4];
    const float* W3 = (const float*)d_in[5];
    float* out = (float*)d_out;
    const int B = in_sizes[0] / 4;

    cudaFuncSetAttribute(lnn_kernel,
                         cudaFuncAttributeMaxDynamicSharedMemorySize,
                         SMEM_TOTAL);
    lnn_kernel<<<296, NTHR, SMEM_TOTAL>>>(X, W1, b1, W2, b2, W3, out, B);
}

// round 16
// speedup vs baseline: 1.0588x; 1.0588x over previous
#include <cuda_runtime.h>
#include <cuda_fp16.h>
#include <cstdint>

#define NTHR 256

// ---- shared memory byte offsets ----
#define BB_HI 0                 // W2 [j][k] fp16 (both GEMMs), 32KB
#define H1_OF (32*1024)         // H1 tile [s][j] fp16, 128 rows, 32KB
#define G2_OF (64*1024)         // G2 tile [s][k] fp16, 128 rows, 32KB
#define OW1   (96*1024)         // 4*128 floats
#define OB1   (OW1 + 2048)
#define OB2   (OB1 + 512)
#define OW3   (OB2 + 512)
#define OTRIG (OW3 + 512)       // 128 * 8 floats = 4KB
#define OPF   (OTRIG + 128*8*4) // 4 * 128 * 4 floats = 8KB
#define SMEM_TOTAL (OPF + 4*128*4*4)

__device__ unsigned int g_ctr  = 0;   // tile work queue
__device__ unsigned int g_done = 0;   // CTA exit counter (for self-reset)

__device__ __forceinline__ uint32_t smem_u32(const void* p) {
    uint32_t a;
    asm("{ .reg .u64 t; cvta.to.shared.u64 t, %1; cvt.u32.u64 %0, t; }"
        : "=r"(a) : "l"(p));
    return a;
}
__device__ __forceinline__ float ftanh(float x) {
    float y;
    asm("tanh.approx.f32 %0, %1;" : "=f"(y) : "f"(x));
    return y;
}
// swizzled byte offset of 16B chunk (row r, chunk) in a [rows]x128 fp16 tile
__device__ __forceinline__ uint32_t swz(int r, int chunk) {
    return (uint32_t)((r << 8) + (((chunk ^ (r & 7)) & 15) << 4));
}
__device__ __forceinline__ uint32_t helem(int r, int c) {
    return swz(r, c >> 3) + ((c & 7) << 1);
}
__device__ __forceinline__ uint32_t packh2(float x0, float x1) {
    const __half2 h = __floats2half2_rn(x0, x1);
    return *(const uint32_t*)&h;
}
__device__ __forceinline__ void ldsm4(uint32_t& r0, uint32_t& r1,
                                      uint32_t& r2, uint32_t& r3, uint32_t a) {
    asm volatile("ldmatrix.sync.aligned.m8n8.x4.shared.b16 {%0,%1,%2,%3}, [%4];"
                 : "=r"(r0), "=r"(r1), "=r"(r2), "=r"(r3) : "r"(a));
}
__device__ __forceinline__ void ldsm4t(uint32_t& r0, uint32_t& r1,
                                       uint32_t& r2, uint32_t& r3, uint32_t a) {
    asm volatile("ldmatrix.sync.aligned.m8n8.x4.trans.shared.b16 {%0,%1,%2,%3}, [%4];"
                 : "=r"(r0), "=r"(r1), "=r"(r2), "=r"(r3) : "r"(a));
}
__device__ __forceinline__ void stsm4(uint32_t a, uint32_t r0, uint32_t r1,
                                      uint32_t r2, uint32_t r3) {
    asm volatile("stmatrix.sync.aligned.m8n8.x4.shared.b16 [%0], {%1,%2,%3,%4};"
                 :: "r"(a), "r"(r0), "r"(r1), "r"(r2), "r"(r3) : "memory");
}
__device__ __forceinline__ void mma16816(float d[4],
                                         uint32_t a0, uint32_t a1,
                                         uint32_t a2, uint32_t a3,
                                         uint32_t b0, uint32_t b1) {
    asm volatile(
        "mma.sync.aligned.m16n8k16.row.col.f32.f16.f16.f32 "
        "{%0,%1,%2,%3}, {%4,%5,%6,%7}, {%8,%9}, {%0,%1,%2,%3};"
        : "+f"(d[0]), "+f"(d[1]), "+f"(d[2]), "+f"(d[3])
        : "r"(a0), "r"(a1), "r"(a2), "r"(a3), "r"(b0), "r"(b1));
}

// D(128x128) = A(128x128) @ op(B); plain fp16 single term.
// 8 warps in 2x4 grid: warp computes m64 x n32 (mt=4).
// TRANSB: B memory [kdim][n]; else [n][kdim].
template <bool TRANSB>
__device__ __forceinline__ void gemm_tile(uint32_t sb, uint32_t Aoff, uint32_t Bo,
                                          int mbase, int nbase, int lane,
                                          float acc[4][4][4]) {
    #pragma unroll
    for (int mt = 0; mt < 4; mt++)
        #pragma unroll
        for (int nt = 0; nt < 4; nt++)
            #pragma unroll
            for (int e = 0; e < 4; e++) acc[mt][nt][e] = 0.0f;

    #pragma unroll
    for (int k = 0; k < 8; k++) {
        const int cb = k * 2;
        uint32_t bH[4][2];
        #pragma unroll
        for (int p = 0; p < 2; p++) {
            const int ntl   = 2 * p + ((lane >> 4) & 1);
            const int khalf = (lane >> 3) & 1;
            if (TRANSB) {
                const int r = k * 16 + khalf * 8 + (lane & 7);
                const uint32_t off = swz(r, (nbase + ntl * 8) >> 3);
                ldsm4t(bH[2*p][0], bH[2*p][1], bH[2*p+1][0], bH[2*p+1][1],
                       sb + Bo + off);
            } else {
                const int r = nbase + ntl * 8 + (lane & 7);
                const uint32_t off = swz(r, cb + khalf);
                ldsm4(bH[2*p][0], bH[2*p][1], bH[2*p+1][0], bH[2*p+1][1],
                      sb + Bo + off);
            }
        }
        #pragma unroll
        for (int mt = 0; mt < 4; mt++) {
            uint32_t aH[4];
            const int r = mbase + mt * 16 + (lane & 15);
            const uint32_t off = swz(r, cb + (lane >> 4));
            ldsm4(aH[0], aH[1], aH[2], aH[3], sb + Aoff + off);
            #pragma unroll
            for (int nt = 0; nt < 4; nt++)
                mma16816(acc[mt][nt], aH[0], aH[1], aH[2], aH[3],
                         bH[nt][0], bH[nt][1]);
        }
    }
}

__global__ void __launch_bounds__(NTHR, 2)
lnn_kernel(const float* __restrict__ X,
           const float* __restrict__ W1, const float* __restrict__ b1,
           const float* __restrict__ W2, const float* __restrict__ b2,
           const float* __restrict__ W3,
           float* __restrict__ out, int B)
{
    extern __shared__ char smem[];
    __shared__ int s_tile;
    const uint32_t sb = smem_u32(smem);
    const int tid  = threadIdx.x;
    const int wid  = tid >> 5;
    const int lane = tid & 31;

    // ---- stage W2 fp16 (single [j][k] layout) + initial tile grab ----
    if (tid == 0) s_tile = (int)atomicAdd(&g_ctr, 1u);
    for (int idx = tid; idx < 128 * 128; idx += NTHR) {
        const int j = idx >> 7, k = idx & 127;
        const __half h = __float2half_rn(W2[idx]);
        *(uint16_t*)(smem + BB_HI + helem(j, k)) = __half_as_ushort(h);
    }
    {
        float* w1s = (float*)(smem + OW1);
        for (int i = tid; i < 512; i += NTHR) w1s[i] = W1[i];
        float* d1 = (float*)(smem + OB1);
        float* d2 = (float*)(smem + OB2);
        float* d3 = (float*)(smem + OW3);
        for (int i = tid; i < 128; i += NTHR) {
            d1[i] = b1[i]; d2[i] = b2[i]; d3[i] = W3[i];
        }
    }
    __syncthreads();

    const float* w1p = (const float*)(smem + OW1);
    const float* b1p = (const float*)(smem + OB1);
    const float* b2p = (const float*)(smem + OB2);
    const float* w3p = (const float*)(smem + OW3);
    float* trig = (float*)(smem + OTRIG);
    float* pfb  = (float*)(smem + OPF);

    const int mg = wid >> 2, ng = wid & 3;     // 2 x 4 warp grid
    const int mbase = mg * 64, nbase = ng * 32;

    // hoisted per-lane constants for epilogues
    float b2v[8], w3v[8], w1a[8][4];
    #pragma unroll
    for (int nt = 0; nt < 4; nt++) {
        const int c = nbase + nt * 8 + 2 * (lane & 3);
        #pragma unroll
        for (int e = 0; e < 2; e++) {
            const int j = c + e;
            b2v[nt * 2 + e] = b2p[j];
            w3v[nt * 2 + e] = w3p[j];
            w1a[nt * 2 + e][0] = w1p[j];
            w1a[nt * 2 + e][1] = w1p[128 + j];
            w1a[nt * 2 + e][2] = w1p[256 + j];
            w1a[nt * 2 + e][3] = w1p[384 + j];
        }
    }

    const int nTiles = (B + 127) >> 7;         // 128-sample tiles

    for (;;) {
        const int t = s_tile;
        if (t >= nTiles) break;

        // ---- 1. fused trig + layer 1: H1 = tanh(feat @ W1 + b1) ----
        {
            const int s = tid & 127;
            const int q = tid >> 7;            // 0..1, owns chunks q*8..q*8+7
            const int g = (t << 7) + s;
            if (g < B) {
                const float4 x = reinterpret_cast<const float4*>(X)[g];
                float s1, c1, s2, c2;
                __sincosf(x.x, &s1, &c1);
                __sincosf(x.y, &s2, &c2);
                if (q == 0) {
                    float* tr = trig + s * 8;
                    tr[0] = s1; tr[1] = c1; tr[2] = s2; tr[3] = c2;
                    tr[4] = x.z; tr[5] = x.w;
                }
                #pragma unroll
                for (int qq = 0; qq < 8; qq++) {
                    const int cc = q * 8 + qq;
                    uint32_t hw[4];
                    #pragma unroll
                    for (int p = 0; p < 4; p++) {
                        const int j = cc * 8 + p * 2;
                        float z0 = b1p[j], z1 = b1p[j + 1];
                        z0 = fmaf(s1, w1p[j], z0);       z1 = fmaf(s1, w1p[j + 1], z1);
                        z0 = fmaf(c1, w1p[128 + j], z0); z1 = fmaf(c1, w1p[129 + j], z1);
                        z0 = fmaf(s2, w1p[256 + j], z0); z1 = fmaf(s2, w1p[257 + j], z1);
                        z0 = fmaf(c2, w1p[384 + j], z0); z1 = fmaf(c2, w1p[385 + j], z1);
                        hw[p] = packh2(ftanh(z0), ftanh(z1));
                    }
                    const uint32_t off = swz(s, cc);
                    *(uint4*)(smem + H1_OF + off) =
                        make_uint4(hw[0], hw[1], hw[2], hw[3]);
                }
            }
        }
        __syncthreads();

        // ---- 2. GEMM1: Z2 = H1 @ W2 (B via trans ldmatrix on [j][k]) ----
        float acc[4][4][4];
        gemm_tile<true>(sb, H1_OF, BB_HI, mbase, nbase, lane, acc);

        // ---- 3. epilogue 1: G2 = W3*(1-tanh(Z2+b2)^2) -> G2 (stmatrix) ----
        #pragma unroll
        for (int mt = 0; mt < 4; mt++)
            #pragma unroll
            for (int hf = 0; hf < 2; hf++) {
                uint32_t rr[4];
                #pragma unroll
                for (int nt = 0; nt < 4; nt++) {
                    const float z0 = acc[mt][nt][hf * 2]     + b2v[nt * 2];
                    const float z1 = acc[mt][nt][hf * 2 + 1] + b2v[nt * 2 + 1];
                    const float t0 = ftanh(z0), t1 = ftanh(z1);
                    const float g0 = w3v[nt * 2]     * (1.0f - t0 * t0);
                    const float g1 = w3v[nt * 2 + 1] * (1.0f - t1 * t1);
                    rr[nt] = packh2(g0, g1);
                }
                const int row = mbase + mt * 16 + hf * 8 + (lane & 7);
                const uint32_t addr =
                    sb + G2_OF + swz(row, (nbase >> 3) + (lane >> 3));
                stsm4(addr, rr[0], rr[1], rr[2], rr[3]);
            }
        __syncthreads();

        // ---- 4. GEMM2: G1pre = G2 @ W2^T (B non-trans on [j][k]) ----
        gemm_tile<false>(sb, G2_OF, BB_HI, mbase, nbase, lane, acc);

        // ---- 5. epilogue 2: h1 fragments via ldmatrix; pf_i = sum W1*g1 ----
        #pragma unroll
        for (int mt = 0; mt < 4; mt++)
            #pragma unroll
            for (int hf = 0; hf < 2; hf++) {
                const int lrow = mbase + mt * 16 + hf * 8 + (lane & 7);
                uint32_t hfrag[4];
                ldsm4(hfrag[0], hfrag[1], hfrag[2], hfrag[3],
                      sb + H1_OF + swz(lrow, (nbase >> 3) + (lane >> 3)));
                float pf0 = 0.f, pf1 = 0.f, pf2 = 0.f, pf3 = 0.f;
                #pragma unroll
                for (int nt = 0; nt < 4; nt++) {
                    const float2 fh = __half22float2(*(const __half2*)&hfrag[nt]);
                    const float hv[2] = {fh.x, fh.y};
                    #pragma unroll
                    for (int e = 0; e < 2; e++) {
                        const float pre = acc[mt][nt][hf * 2 + e];
                        const float h = hv[e];
                        const float g1 = (1.0f - h * h) * pre;
                        const float* wa = w1a[nt * 2 + e];
                        pf0 = fmaf(wa[0], g1, pf0); pf1 = fmaf(wa[1], g1, pf1);
                        pf2 = fmaf(wa[2], g1, pf2); pf3 = fmaf(wa[3], g1, pf3);
                    }
                }
                pf0 += __shfl_xor_sync(0xffffffffu, pf0, 1);
                pf1 += __shfl_xor_sync(0xffffffffu, pf1, 1);
                pf2 += __shfl_xor_sync(0xffffffffu, pf2, 1);
                pf3 += __shfl_xor_sync(0xffffffffu, pf3, 1);
                pf0 += __shfl_xor_sync(0xffffffffu, pf0, 2);
                pf1 += __shfl_xor_sync(0xffffffffu, pf1, 2);
                pf2 += __shfl_xor_sync(0xffffffffu, pf2, 2);
                pf3 += __shfl_xor_sync(0xffffffffu, pf3, 2);
                const int row = mbase + mt * 16 + (lane >> 2) + hf * 8;
                if ((lane & 3) == 0)
                    *(float4*)(pfb + (ng * 128 + row) * 4) =
                        make_float4(pf0, pf1, pf2, pf3);
            }
        __syncthreads();

        // ---- 6. combine partials + closure + 2x2 solve; grab next tile ----
        if (tid == 0) s_tile = (int)atomicAdd(&g_ctr, 1u);
        if (tid < 128) {
            const int gidx = (t << 7) + tid;
            if (gidx < B) {
                float p0 = 0.f, p1 = 0.f, p2 = 0.f, p3 = 0.f;
                #pragma unroll
                for (int q = 0; q < 4; q++) {
                    const float4 v = *(const float4*)(pfb + (q * 128 + tid) * 4);
                    p0 += v.x; p1 += v.y; p2 += v.z; p3 += v.w;
                }
                const float* tr = trig + tid * 8;
                const float s1 = tr[0], c1 = tr[1], s2 = tr[2], c2 = tr[3];
                const float w1v = tr[4], w2v = tr[5];
                const float sd = s1 * c2 - c1 * s2;
                const float cd = c1 * c2 + s1 * s2;
                const float dV1 = p0 * c1 - p1 * s1;
                const float dV2 = p2 * c2 - p3 * s2;
                const float dw = w2v - w1v;
                const float rhs1 = -w1v * w2v * sd - dV1 - w2v * sd * dw;
                const float rhs2 =  w1v * w2v * sd - dV2 - w1v * sd * dw;
                const float det = 2.0f - cd * cd;
                const float inv = __fdividef(1.0f, det);
                const float q1 = (rhs1 - cd * rhs2) * inv;
                const float q2 = (2.0f * rhs2 - cd * rhs1) * inv;
                reinterpret_cast<float4*>(out)[gidx] = make_float4(w1v, w2v, q1, q2);
            }
        }
        __syncthreads();
    }

    // ---- self-reset of the work queue for graph replays ----
    // Total increments per launch = nTiles-successes + one failing grab per
    // CTA-iteration; the LAST exiting CTA zeroes both counters.
    if (tid == 0) {
        __threadfence();
        const unsigned int d = atomicAdd(&g_done, 1u);
        if (d == gridDim.x - 1u) {
            g_ctr  = 0u;
            g_done = 0u;
            __threadfence();
        }
    }
}

extern "C" void kernel_launch(void* const* d_in, const int* in_sizes, int n_in,
                              void* d_out, int out_size)
{
    const float* X  = (const float*)d_in[0];
    const float* W1 = (const float*)d_in[1];
    const float* b1 = (const float*)d_in[2];
    const float* W2 = (const float*)d_in[3];
    const float* b2 = (const float*)d_in[4];
    const float* W3 = (const float*)d_in[5];
    float* out = (float*)d_out;
    const int B = in_sizes[0] / 4;

    cudaFuncSetAttribute(lnn_kernel,
                         cudaFuncAttributeMaxDynamicSharedMemorySize,
                         SMEM_TOTAL);
    lnn_kernel<<<296, NTHR, SMEM_TOTAL>>>(X, W1, b1, W2, b2, W3, out, B);
}

// round 17
// speedup vs baseline: 1.1528x; 1.0887x over previous
#include <cuda_runtime.h>
#include <cuda_fp16.h>
#include <cstdint>

#define NTHR 256

// ---- shared memory byte offsets ----
#define BB_HI 0                 // W2 [j][k] fp16 (both GEMMs), 32KB
#define H1_OF (32*1024)         // H1 tile [s][j] fp16 (then g1), 32KB
#define G2_OF (64*1024)         // G2 tile [s][k] fp16, 32KB
#define OW1   (96*1024)         // W1 fp32, 4*128 floats
#define OB1   (OW1 + 2048)
#define OB2   (OB1 + 512)
#define OW3   (OB2 + 512)
#define OW1H  (OW3 + 512)       // W1 fp16 [8 rows (4 pad)] x 128, swizzled, 2KB
#define OTRIG (OW1H + 2048)     // 128 * 8 floats = 4KB
#define SMEM_TOTAL (OTRIG + 128*8*4)

__device__ __forceinline__ uint32_t smem_u32(const void* p) {
    uint32_t a;
    asm("{ .reg .u64 t; cvta.to.shared.u64 t, %1; cvt.u32.u64 %0, t; }"
        : "=r"(a) : "l"(p));
    return a;
}
__device__ __forceinline__ float ftanh(float x) {
    float y;
    asm("tanh.approx.f32 %0, %1;" : "=f"(y) : "f"(x));
    return y;
}
// swizzled byte offset of 16B chunk (row r, chunk) in a [rows]x128 fp16 tile
__device__ __forceinline__ uint32_t swz(int r, int chunk) {
    return (uint32_t)((r << 8) + (((chunk ^ (r & 7)) & 15) << 4));
}
__device__ __forceinline__ uint32_t helem(int r, int c) {
    return swz(r, c >> 3) + ((c & 7) << 1);
}
__device__ __forceinline__ uint32_t packh2(float x0, float x1) {
    const __half2 h = __floats2half2_rn(x0, x1);
    return *(const uint32_t*)&h;
}
__device__ __forceinline__ void ldsm4(uint32_t& r0, uint32_t& r1,
                                      uint32_t& r2, uint32_t& r3, uint32_t a) {
    asm volatile("ldmatrix.sync.aligned.m8n8.x4.shared.b16 {%0,%1,%2,%3}, [%4];"
                 : "=r"(r0), "=r"(r1), "=r"(r2), "=r"(r3) : "r"(a));
}
__device__ __forceinline__ void ldsm4t(uint32_t& r0, uint32_t& r1,
                                       uint32_t& r2, uint32_t& r3, uint32_t a) {
    asm volatile("ldmatrix.sync.aligned.m8n8.x4.trans.shared.b16 {%0,%1,%2,%3}, [%4];"
                 : "=r"(r0), "=r"(r1), "=r"(r2), "=r"(r3) : "r"(a));
}
__device__ __forceinline__ void ldsm2(uint32_t& r0, uint32_t& r1, uint32_t a) {
    asm volatile("ldmatrix.sync.aligned.m8n8.x2.shared.b16 {%0,%1}, [%2];"
                 : "=r"(r0), "=r"(r1) : "r"(a));
}
__device__ __forceinline__ void stsm4(uint32_t a, uint32_t r0, uint32_t r1,
                                      uint32_t r2, uint32_t r3) {
    asm volatile("stmatrix.sync.aligned.m8n8.x4.shared.b16 [%0], {%1,%2,%3,%4};"
                 :: "r"(a), "r"(r0), "r"(r1), "r"(r2), "r"(r3) : "memory");
}
__device__ __forceinline__ void mma16816(float d[4],
                                         uint32_t a0, uint32_t a1,
                                         uint32_t a2, uint32_t a3,
                                         uint32_t b0, uint32_t b1) {
    asm volatile(
        "mma.sync.aligned.m16n8k16.row.col.f32.f16.f16.f32 "
        "{%0,%1,%2,%3}, {%4,%5,%6,%7}, {%8,%9}, {%0,%1,%2,%3};"
        : "+f"(d[0]), "+f"(d[1]), "+f"(d[2]), "+f"(d[3])
        : "r"(a0), "r"(a1), "r"(a2), "r"(a3), "r"(b0), "r"(b1));
}

// D(128x128) = A(128x128) @ op(B); plain fp16 single term.
// 8 warps in 2x4 grid: warp computes m64 x n32 (mt=4).
// TRANSB: B memory [kdim][n]; else [n][kdim].
template <bool TRANSB>
__device__ __forceinline__ void gemm_tile(uint32_t sb, uint32_t Aoff, uint32_t Bo,
                                          int mbase, int nbase, int lane,
                                          float acc[4][4][4]) {
    #pragma unroll
    for (int mt = 0; mt < 4; mt++)
        #pragma unroll
        for (int nt = 0; nt < 4; nt++)
            #pragma unroll
            for (int e = 0; e < 4; e++) acc[mt][nt][e] = 0.0f;

    #pragma unroll
    for (int k = 0; k < 8; k++) {
        const int cb = k * 2;
        uint32_t bH[4][2];
        #pragma unroll
        for (int p = 0; p < 2; p++) {
            const int ntl   = 2 * p + ((lane >> 4) & 1);
            const int khalf = (lane >> 3) & 1;
            if (TRANSB) {
                const int r = k * 16 + khalf * 8 + (lane & 7);
                const uint32_t off = swz(r, (nbase + ntl * 8) >> 3);
                ldsm4t(bH[2*p][0], bH[2*p][1], bH[2*p+1][0], bH[2*p+1][1],
                       sb + Bo + off);
            } else {
                const int r = nbase + ntl * 8 + (lane & 7);
                const uint32_t off = swz(r, cb + khalf);
                ldsm4(bH[2*p][0], bH[2*p][1], bH[2*p+1][0], bH[2*p+1][1],
                      sb + Bo + off);
            }
        }
        #pragma unroll
        for (int mt = 0; mt < 4; mt++) {
            uint32_t aH[4];
            const int r = mbase + mt * 16 + (lane & 15);
            const uint32_t off = swz(r, cb + (lane >> 4));
            ldsm4(aH[0], aH[1], aH[2], aH[3], sb + Aoff + off);
            #pragma unroll
            for (int nt = 0; nt < 4; nt++)
                mma16816(acc[mt][nt], aH[0], aH[1], aH[2], aH[3],
                         bH[nt][0], bH[nt][1]);
        }
    }
}

__global__ void __launch_bounds__(NTHR, 2)
lnn_kernel(const float* __restrict__ X,
           const float* __restrict__ W1, const float* __restrict__ b1,
           const float* __restrict__ W2, const float* __restrict__ b2,
           const float* __restrict__ W3,
           float* __restrict__ out, int B)
{
    extern __shared__ char smem[];
    const uint32_t sb = smem_u32(smem);
    const int tid  = threadIdx.x;
    const int wid  = tid >> 5;
    const int lane = tid & 31;

    // ---- stage W2 fp16 (single [j][k] layout) ----
    for (int idx = tid; idx < 128 * 128; idx += NTHR) {
        const int j = idx >> 7, k = idx & 127;
        const __half h = __float2half_rn(W2[idx]);
        *(uint16_t*)(smem + BB_HI + helem(j, k)) = __half_as_ushort(h);
    }
    {
        float* w1s = (float*)(smem + OW1);
        for (int i = tid; i < 512; i += NTHR) w1s[i] = W1[i];
        float* d1 = (float*)(smem + OB1);
        float* d2 = (float*)(smem + OB2);
        float* d3 = (float*)(smem + OW3);
        for (int i = tid; i < 128; i += NTHR) {
            d1[i] = b1[i]; d2[i] = b2[i]; d3[i] = W3[i];
        }
        // W1 fp16 padded to 8 rows for GEMM3 B operand: B[n=i][k=j]
        for (int idx = tid; idx < 8 * 128; idx += NTHR) {
            const int i = idx >> 7, j = idx & 127;
            const float v = (i < 4) ? W1[i * 128 + j] : 0.0f;
            *(uint16_t*)(smem + OW1H + helem(i, j)) =
                __half_as_ushort(__float2half_rn(v));
        }
    }
    __syncthreads();

    const float* w1p = (const float*)(smem + OW1);
    const float* b1p = (const float*)(smem + OB1);
    const float* b2p = (const float*)(smem + OB2);
    const float* w3p = (const float*)(smem + OW3);
    float* trig = (float*)(smem + OTRIG);

    const int mg = wid >> 2, ng = wid & 3;     // 2 x 4 warp grid
    const int mbase = mg * 64, nbase = ng * 32;

    // hoisted per-lane constants for epilogue 1
    float b2v[8], w3v[8];
    #pragma unroll
    for (int nt = 0; nt < 4; nt++) {
        const int c = nbase + nt * 8 + 2 * (lane & 3);
        #pragma unroll
        for (int e = 0; e < 2; e++) {
            b2v[nt * 2 + e] = b2p[c + e];
            w3v[nt * 2 + e] = w3p[c + e];
        }
    }

    const int nTiles = (B + 127) >> 7;         // 128-sample tiles
    for (int t = blockIdx.x; t < nTiles; t += gridDim.x) {
        // ---- 1. fused trig + layer 1: H1 = tanh(feat @ W1 + b1) ----
        {
            const int s = tid & 127;
            const int q = tid >> 7;            // 0..1, owns chunks q*8..q*8+7
            const int g = (t << 7) + s;
            if (g < B) {
                const float4 x = reinterpret_cast<const float4*>(X)[g];
                float s1, c1, s2, c2;
                __sincosf(x.x, &s1, &c1);
                __sincosf(x.y, &s2, &c2);
                if (q == 0) {
                    float* tr = trig + s * 8;
                    tr[0] = s1; tr[1] = c1; tr[2] = s2; tr[3] = c2;
                    tr[4] = x.z; tr[5] = x.w;
                }
                #pragma unroll
                for (int qq = 0; qq < 8; qq++) {
                    const int cc = q * 8 + qq;
                    uint32_t hw[4];
                    #pragma unroll
                    for (int p = 0; p < 4; p++) {
                        const int j = cc * 8 + p * 2;
                        float z0 = b1p[j], z1 = b1p[j + 1];
                        z0 = fmaf(s1, w1p[j], z0);       z1 = fmaf(s1, w1p[j + 1], z1);
                        z0 = fmaf(c1, w1p[128 + j], z0); z1 = fmaf(c1, w1p[129 + j], z1);
                        z0 = fmaf(s2, w1p[256 + j], z0); z1 = fmaf(s2, w1p[257 + j], z1);
                        z0 = fmaf(c2, w1p[384 + j], z0); z1 = fmaf(c2, w1p[385 + j], z1);
                        hw[p] = packh2(ftanh(z0), ftanh(z1));
                    }
                    const uint32_t off = swz(s, cc);
                    *(uint4*)(smem + H1_OF + off) =
                        make_uint4(hw[0], hw[1], hw[2], hw[3]);
                }
            }
        }
        __syncthreads();

        // ---- 2. GEMM1: Z2 = H1 @ W2 ; epilogue 1 -> G2 (stmatrix) ----
        float acc[4][4][4];
        gemm_tile<true>(sb, H1_OF, BB_HI, mbase, nbase, lane, acc);

        #pragma unroll
        for (int mt = 0; mt < 4; mt++)
            #pragma unroll
            for (int hf = 0; hf < 2; hf++) {
                uint32_t rr[4];
                #pragma unroll
                for (int nt = 0; nt < 4; nt++) {
                    const float z0 = acc[mt][nt][hf * 2]     + b2v[nt * 2];
                    const float z1 = acc[mt][nt][hf * 2 + 1] + b2v[nt * 2 + 1];
                    const float t0 = ftanh(z0), t1 = ftanh(z1);
                    const float g0 = w3v[nt * 2]     * (1.0f - t0 * t0);
                    const float g1 = w3v[nt * 2 + 1] * (1.0f - t1 * t1);
                    rr[nt] = packh2(g0, g1);
                }
                const int row = mbase + mt * 16 + hf * 8 + (lane & 7);
                const uint32_t addr =
                    sb + G2_OF + swz(row, (nbase >> 3) + (lane >> 3));
                stsm4(addr, rr[0], rr[1], rr[2], rr[3]);
            }
        __syncthreads();

        // ---- 3. GEMM2: G1pre = G2 @ W2^T ; epilogue 2: g1 -> H1 buf ----
        gemm_tile<false>(sb, G2_OF, BB_HI, mbase, nbase, lane, acc);

        #pragma unroll
        for (int mt = 0; mt < 4; mt++)
            #pragma unroll
            for (int hf = 0; hf < 2; hf++) {
                const int lrow = mbase + mt * 16 + hf * 8 + (lane & 7);
                const uint32_t addr =
                    sb + H1_OF + swz(lrow, (nbase >> 3) + (lane >> 3));
                uint32_t hfrag[4];
                ldsm4(hfrag[0], hfrag[1], hfrag[2], hfrag[3], addr);
                uint32_t rr[4];
                #pragma unroll
                for (int nt = 0; nt < 4; nt++) {
                    const float2 fh = __half22float2(*(const __half2*)&hfrag[nt]);
                    const float g0 = (1.0f - fh.x * fh.x) * acc[mt][nt][hf * 2];
                    const float g1 = (1.0f - fh.y * fh.y) * acc[mt][nt][hf * 2 + 1];
                    rr[nt] = packh2(g0, g1);
                }
                stsm4(addr, rr[0], rr[1], rr[2], rr[3]);
            }
        __syncthreads();

        // ---- 4. GEMM3: PF[128x4] = g1 @ W1^T (ng==0 warps) + closure ----
        if (ng == 0) {
            float acc3[4][4];
            #pragma unroll
            for (int mt = 0; mt < 4; mt++)
                #pragma unroll
                for (int e = 0; e < 4; e++) acc3[mt][e] = 0.0f;

            #pragma unroll
            for (int k = 0; k < 8; k++) {
                const int cb = k * 2;
                uint32_t b0, b1v;
                {
                    const int r = lane & 7;
                    const int khalf = (lane >> 3) & 1;
                    ldsm2(b0, b1v, sb + OW1H + swz(r, cb + khalf));
                }
                #pragma unroll
                for (int mt = 0; mt < 4; mt++) {
                    uint32_t aH[4];
                    const int r = mbase + mt * 16 + (lane & 15);
                    const uint32_t off = swz(r, cb + (lane >> 4));
                    ldsm4(aH[0], aH[1], aH[2], aH[3], sb + H1_OF + off);
                    mma16816(acc3[mt], aH[0], aH[1], aH[2], aH[3], b0, b1v);
                }
            }

            // closure: lane&3==0 holds (pf0,pf1); lane&3==1 holds (pf2,pf3)
            #pragma unroll
            for (int mt = 0; mt < 4; mt++)
                #pragma unroll
                for (int hf = 0; hf < 2; hf++) {
                    const float v0 = acc3[mt][hf * 2];
                    const float v1 = acc3[mt][hf * 2 + 1];
                    const float p2 = __shfl_down_sync(0xffffffffu, v0, 1);
                    const float p3 = __shfl_down_sync(0xffffffffu, v1, 1);
                    if ((lane & 3) == 0) {
                        const int row = mbase + mt * 16 + (lane >> 2) + hf * 8;
                        const int gidx = (t << 7) + row;
                        if (gidx < B) {
                            const float* tr = trig + row * 8;
                            const float s1 = tr[0], c1 = tr[1];
                            const float s2 = tr[2], c2 = tr[3];
                            const float w1v = tr[4], w2v = tr[5];
                            const float sd = s1 * c2 - c1 * s2;
                            const float cd = c1 * c2 + s1 * s2;
                            const float dV1 = v0 * c1 - v1 * s1;
                            const float dV2 = p2 * c2 - p3 * s2;
                            const float dw = w2v - w1v;
                            const float rhs1 = -w1v * w2v * sd - dV1 - w2v * sd * dw;
                            const float rhs2 =  w1v * w2v * sd - dV2 - w1v * sd * dw;
                            const float det = 2.0f - cd * cd;
                            const float inv = __fdividef(1.0f, det);
                            const float q1 = (rhs1 - cd * rhs2) * inv;
                            const float q2 = (2.0f * rhs2 - cd * rhs1) * inv;
                            reinterpret_cast<float4*>(out)[gidx] =
                                make_float4(w1v, w2v, q1, q2);
                        }
                    }
                }
        }
        __syncthreads();   // protect H1(g1)/trig before next tile
    }
}

extern "C" void kernel_launch(void* const* d_in, const int* in_sizes, int n_in,
                              void* d_out, int out_size)
{
    const float* X  = (const float*)d_in[0];
    const float* W1 = (const float*)d_in[1];
    const float* b1 = (const float*)d_in[2];
    const float* W2 = (const float*)d_in[3];
    const float* b2 = (const float*)d_in[4];
    const float* W3 = (const float*)d_in[5];
    float* out = (float*)d_out;
    const int B = in_sizes[0] / 4;

    cudaFuncSetAttribute(lnn_kernel,
                         cudaFuncAttributeMaxDynamicSharedMemorySize,
                         SMEM_TOTAL);
    lnn_kernel<<<296, NTHR, SMEM_TOTAL>>>(X, W1, b1, W2, b2, W3, out, B);
}